// round 13
// baseline (speedup 1.0000x reference)
#include <cuda_runtime.h>
#include <math.h>

#define NTOK 2048
#define CDIM 1024
#define NHEADS 16
#define HD 64
#define NCAM 2
#define NPER 1024
#define LDT 20

// ---------------- scratch ----------------
static __device__ float g_qkv[(size_t)NTOK * 3 * CDIM];
static __device__ float g_q[(size_t)NHEADS * NTOK * HD];
static __device__ float g_khl[(size_t)NHEADS * NTOK * HD * 2];   // [h][n][2d] hi/lo
static __device__ float g_vhl[(size_t)NHEADS * HD * NTOK * 2];   // [h][d][2n] hi/lo
static __device__ float g_y[(size_t)NTOK * CDIM];
static __device__ float g_P[NCAM * 16];
static __device__ float g_Pinv[NCAM * 16];
static __device__ float g_freqs[8];

// ---------------- helpers ----------------
__device__ __forceinline__ float f2tf32(float x) {
    unsigned u;
    asm("cvt.rna.tf32.f32 %0, %1;" : "=r"(u) : "f"(x));
    return __uint_as_float(u);
}
__device__ __forceinline__ void mma_tf32(float* d, const unsigned* a, const unsigned* b) {
    asm volatile(
        "mma.sync.aligned.m16n8k8.row.col.f32.tf32.tf32.f32 "
        "{%0,%1,%2,%3}, {%4,%5,%6,%7}, {%8,%9}, {%0,%1,%2,%3};\n"
        : "+f"(d[0]), "+f"(d[1]), "+f"(d[2]), "+f"(d[3])
        : "r"(a[0]), "r"(a[1]), "r"(a[2]), "r"(a[3]), "r"(b[0]), "r"(b[1]));
}
__device__ __forceinline__ void cp16(float* dst, const float* src) {
    unsigned d = (unsigned)__cvta_generic_to_shared(dst);
    asm volatile("cp.async.cg.shared.global [%0], [%1], 16;\n" :: "r"(d), "l"(src));
}

// ---------------- camera matrices + freq table ----------------
__global__ void setup_mats(const float* __restrict__ ext, const float* __restrict__ Ks) {
    int c = threadIdx.x;
    if (c < 8) g_freqs[c] = powf(100.f, -(float)c * 0.125f);
    if (c >= NCAM) return;
    const float sx = 2.0f / 448.0f, sy = 2.0f / 448.0f;
    float fx = Ks[c * 9 + 0], cx = Ks[c * 9 + 2];
    float fy = Ks[c * 9 + 4], cy = Ks[c * 9 + 5];
    float Kn[4][4] = {};
    Kn[0][0] = fx * sx; Kn[0][2] = cx * sx - 1.0f;
    Kn[1][1] = fy * sy; Kn[1][2] = cy * sy - 1.0f;
    Kn[2][2] = 1.0f;    Kn[3][3] = 1.0f;
    float P[4][4];
    for (int i = 0; i < 4; i++)
        for (int j = 0; j < 4; j++) {
            float s = 0.f;
            for (int k = 0; k < 4; k++) s += Kn[i][k] * ext[c * 16 + k * 4 + j];
            P[i][j] = s;
            g_P[c * 16 + i * 4 + j] = s;
        }
    float M[4][8];
    for (int i = 0; i < 4; i++)
        for (int j = 0; j < 4; j++) { M[i][j] = P[i][j]; M[i][4 + j] = (i == j) ? 1.f : 0.f; }
    for (int col = 0; col < 4; col++) {
        int piv = col;
        for (int r = col + 1; r < 4; r++)
            if (fabsf(M[r][col]) > fabsf(M[piv][col])) piv = r;
        if (piv != col)
            for (int j = 0; j < 8; j++) { float t = M[col][j]; M[col][j] = M[piv][j]; M[piv][j] = t; }
        float inv = 1.0f / M[col][col];
        for (int j = 0; j < 8; j++) M[col][j] *= inv;
        for (int r = 0; r < 4; r++) if (r != col) {
            float f = M[r][col];
            for (int j = 0; j < 8; j++) M[r][j] -= f * M[col][j];
        }
    }
    for (int i = 0; i < 4; i++)
        for (int j = 0; j < 4; j++) g_Pinv[c * 16 + i * 4 + j] = M[i][4 + j];
}

// ---------------- TF32x3 GEMM NT, BK=16, double-buffered, 2 CTAs/SM ----------------
#define GSTG (4 * 128 * LDT)
#define SM_NT (2 * GSTG * 4)
__global__ __launch_bounds__(256, 2) void gemm_nt_tf32(
    const float* __restrict__ A, const float* __restrict__ B, float* __restrict__ C,
    int M, int N, int K, const float* __restrict__ bias)
{
    extern __shared__ float sm[];
    const int tid = threadIdx.x;
    const int lane = tid & 31, warp = tid >> 5;
    const int g = lane >> 2, t = lane & 3;
    const int wm = (warp >> 2) * 64, wn = (warp & 3) * 32;
    const int row0 = blockIdx.y * 128;
    const int col0 = blockIdx.x * 128;
    const int lr = tid >> 1;              // 0..127
    const int lc4 = (tid & 1) * 8;        // 0 or 8 (two float4 per row-half)
    float acc[4][4][4];
    #pragma unroll
    for (int i = 0; i < 4; i++)
        #pragma unroll
        for (int j = 0; j < 4; j++)
            #pragma unroll
            for (int e = 0; e < 4; e++) acc[i][j][e] = 0.f;

    float4 avr[2], bvr[2];
    #pragma unroll
    for (int i = 0; i < 2; i++) {
        avr[i] = *(const float4*)(A + (size_t)(row0 + lr) * K + lc4 + i * 4);
        bvr[i] = *(const float4*)(B + (size_t)(col0 + lr) * K + lc4 + i * 4);
    }
    {
        float* Ah = sm; float* Al = Ah + 128 * LDT;
        float* Bh = Al + 128 * LDT; float* Bl = Bh + 128 * LDT;
        #pragma unroll
        for (int i = 0; i < 2; i++) {
            float4 av = avr[i], bv = bvr[i];
            float4 ah = {f2tf32(av.x), f2tf32(av.y), f2tf32(av.z), f2tf32(av.w)};
            float4 al = {f2tf32(av.x - ah.x), f2tf32(av.y - ah.y), f2tf32(av.z - ah.z), f2tf32(av.w - ah.w)};
            float4 bh = {f2tf32(bv.x), f2tf32(bv.y), f2tf32(bv.z), f2tf32(bv.w)};
            float4 bl = {f2tf32(bv.x - bh.x), f2tf32(bv.y - bh.y), f2tf32(bv.z - bh.z), f2tf32(bv.w - bh.w)};
            *(float4*)&Ah[lr * LDT + lc4 + i * 4] = ah;
            *(float4*)&Al[lr * LDT + lc4 + i * 4] = al;
            *(float4*)&Bh[lr * LDT + lc4 + i * 4] = bh;
            *(float4*)&Bl[lr * LDT + lc4 + i * 4] = bl;
        }
    }
    __syncthreads();

    int buf = 0;
    for (int kt = 0; kt < K; kt += 16) {
        bool more = (kt + 16 < K);
        if (more) {
            #pragma unroll
            for (int i = 0; i < 2; i++) {
                avr[i] = *(const float4*)(A + (size_t)(row0 + lr) * K + kt + 16 + lc4 + i * 4);
                bvr[i] = *(const float4*)(B + (size_t)(col0 + lr) * K + kt + 16 + lc4 + i * 4);
            }
        }
        const float* Ah = sm + buf * GSTG;
        const float* Al = Ah + 128 * LDT;
        const float* Bh = Al + 128 * LDT;
        const float* Bl = Bh + 128 * LDT;
        #pragma unroll
        for (int kk = 0; kk < 2; kk++) {
            const int kc = kk * 8;
            unsigned bh_[4][2], bl_[4][2];
            #pragma unroll
            for (int nt = 0; nt < 4; nt++) {
                int nrow = (wn + nt * 8 + g) * LDT + kc + t;
                bh_[nt][0] = __float_as_uint(Bh[nrow]); bh_[nt][1] = __float_as_uint(Bh[nrow + 4]);
                bl_[nt][0] = __float_as_uint(Bl[nrow]); bl_[nt][1] = __float_as_uint(Bl[nrow + 4]);
            }
            #pragma unroll
            for (int mt = 0; mt < 4; mt++) {
                int r0 = (wm + mt * 16 + g) * LDT + kc + t;
                int r1 = (wm + mt * 16 + g + 8) * LDT + kc + t;
                unsigned ah_[4] = {__float_as_uint(Ah[r0]), __float_as_uint(Ah[r1]),
                                   __float_as_uint(Ah[r0 + 4]), __float_as_uint(Ah[r1 + 4])};
                unsigned al_[4] = {__float_as_uint(Al[r0]), __float_as_uint(Al[r1]),
                                   __float_as_uint(Al[r0 + 4]), __float_as_uint(Al[r1 + 4])};
                #pragma unroll
                for (int nt = 0; nt < 4; nt++) {
                    mma_tf32(acc[mt][nt], ah_, bh_[nt]);
                    mma_tf32(acc[mt][nt], ah_, bl_[nt]);
                    mma_tf32(acc[mt][nt], al_, bh_[nt]);
                }
            }
        }
        if (more) {
            float* Ah2 = sm + (buf ^ 1) * GSTG;
            float* Al2 = Ah2 + 128 * LDT;
            float* Bh2 = Al2 + 128 * LDT;
            float* Bl2 = Bh2 + 128 * LDT;
            #pragma unroll
            for (int i = 0; i < 2; i++) {
                float4 av = avr[i], bv = bvr[i];
                float4 ah = {f2tf32(av.x), f2tf32(av.y), f2tf32(av.z), f2tf32(av.w)};
                float4 al = {f2tf32(av.x - ah.x), f2tf32(av.y - ah.y), f2tf32(av.z - ah.z), f2tf32(av.w - ah.w)};
                float4 bh = {f2tf32(bv.x), f2tf32(bv.y), f2tf32(bv.z), f2tf32(bv.w)};
                float4 bl = {f2tf32(bv.x - bh.x), f2tf32(bv.y - bh.y), f2tf32(bv.z - bh.z), f2tf32(bv.w - bh.w)};
                *(float4*)&Ah2[lr * LDT + lc4 + i * 4] = ah;
                *(float4*)&Al2[lr * LDT + lc4 + i * 4] = al;
                *(float4*)&Bh2[lr * LDT + lc4 + i * 4] = bh;
                *(float4*)&Bl2[lr * LDT + lc4 + i * 4] = bl;
            }
        }
        __syncthreads();
        buf ^= 1;
    }
    #pragma unroll
    for (int mt = 0; mt < 4; mt++) {
        int r = row0 + wm + mt * 16 + g;
        #pragma unroll
        for (int nt = 0; nt < 4; nt++) {
            int c = col0 + wn + nt * 8 + 2 * t;
            float b0 = 0.f, b1 = 0.f;
            if (bias) { b0 = bias[c]; b1 = bias[c + 1]; }
            float2 o0 = {acc[mt][nt][0] + b0, acc[mt][nt][1] + b1};
            float2 o1 = {acc[mt][nt][2] + b0, acc[mt][nt][3] + b1};
            *(float2*)(C + (size_t)r * N + c) = o0;
            *(float2*)(C + (size_t)(r + 8) * N + c) = o1;
        }
    }
}

// ---------------- q/k/v transform: Q pre-scaled, K/V pre-split hi/lo ----------------
__global__ __launch_bounds__(256) void qkv_transform() {
    int grp = threadIdx.x >> 6;
    int nh = blockIdx.x * 4 + grp;
    int n = nh >> 4;
    int h = nh & 15;
    int d = threadIdx.x & 63;
    __shared__ float sq[4][64], sk[4][64], sv[4][64];
    const float* base = g_qkv + (size_t)n * 3072 + h * 64;
    sq[grp][d] = base[d];
    sk[grp][d] = base[1024 + d];
    sv[grp][d] = base[2048 + d];
    __syncthreads();
    int cam = n / NPER;
    int p = n % NPER;
    float px = (float)(p & 31), py = (float)(p >> 5);
    float oq, ok, ov;
    if (d < 32) {
        int gg = d & ~3, i = d & 3;
        const float* P  = g_P + cam * 16;
        const float* Pi = g_Pinv + cam * 16;
        oq = ok = ov = 0.f;
        #pragma unroll
        for (int j = 0; j < 4; j++) {
            oq += Pi[j * 4 + i] * sq[grp][gg + j];
            float pij = P[i * 4 + j];
            ok += pij * sk[grp][gg + j];
            ov += pij * sv[grp][gg + j];
        }
    } else {
        int r = d - 32, pair = r >> 1, part = r & 1;
        float fr = g_freqs[pair & 7];
        float ang = ((pair < 8) ? px : py) * fr;
        float cc = cosf(ang), ss = sinf(ang);
        int ia = 32 + (pair << 1), ib = ia + 1;
        if (part == 0) { oq = sq[grp][ia] * cc - sq[grp][ib] * ss; ok = sk[grp][ia] * cc - sk[grp][ib] * ss; ov = sv[grp][ia] * cc - sv[grp][ib] * ss; }
        else           { oq = sq[grp][ia] * ss + sq[grp][ib] * cc; ok = sk[grp][ia] * ss + sk[grp][ib] * cc; ov = sv[grp][ia] * ss + sv[grp][ib] * cc; }
    }
    g_q[((size_t)h * NTOK + n) * HD + d] = oq * 0.125f;
    float kh = f2tf32(ok);
    float* kp = g_khl + ((size_t)h * NTOK + n) * 128 + 2 * d;
    kp[0] = kh; kp[1] = f2tf32(ok - kh);
    float vh = f2tf32(ov);
    float* vp = g_vhl + ((size_t)h * HD + d) * (NTOK * 2) + 2 * n;
    vp[0] = vh; vp[1] = f2tf32(ov - vh);
}

// ---------------- Flash attention with fused output transform (raw y) ----------------
#define LDK 136
#define KARR (64 * LDK)
#define FLSTG (2 * KARR)
#define PW_LD 68
#define PPAD (8 * 16 * PW_LD)
#define QLD 68
#define FL_SMEM ((PPAD + 2 * FLSTG) * 4)
#define NKVT (NTOK / 64)
__global__ __launch_bounds__(256, 1) void flash_attn() {
    extern __shared__ float sm[];
    float* Ppad = sm;
    float* KVbase = sm + PPAD;

    const int tid = threadIdx.x;
    const int lane = tid & 31, warp = tid >> 5;
    const int g = lane >> 2, t = lane & 3;
    const int h = blockIdx.y;
    const int qb = blockIdx.x;
    const float* Qg = g_q + ((size_t)h * NTOK + qb * 128) * HD;
    const float* Ksrc = g_khl + (size_t)h * NTOK * 128;
    const float* Vsrc = g_vhl + (size_t)h * HD * (NTOK * 2);

    {
        float* Qs = KVbase;
        int row = tid >> 1, halfq = tid & 1;
        #pragma unroll
        for (int i = 0; i < 4; i++) {
            float4 v = *(const float4*)(Qg + row * 64 + halfq * 32 + i * 8);
            float4 w = *(const float4*)(Qg + row * 64 + halfq * 32 + i * 8 + 4);
            *(float4*)&Qs[row * QLD + halfq * 32 + i * 8] = v;
            *(float4*)&Qs[row * QLD + halfq * 32 + i * 8 + 4] = w;
        }
    }
    __syncthreads();
    unsigned qh[8][4], ql[8][4];
    {
        const float* Qs = KVbase;
        int r0 = (warp * 16 + g) * QLD, r1 = (warp * 16 + g + 8) * QLD;
        #pragma unroll
        for (int kt = 0; kt < 8; kt++) {
            int c = kt * 8 + t;
            float a0 = Qs[r0 + c];
            float a1 = Qs[r1 + c];
            float a2 = Qs[r0 + c + 4];
            float a3 = Qs[r1 + c + 4];
            float h0 = f2tf32(a0), h1 = f2tf32(a1), h2 = f2tf32(a2), h3 = f2tf32(a3);
            qh[kt][0] = __float_as_uint(h0); qh[kt][1] = __float_as_uint(h1);
            qh[kt][2] = __float_as_uint(h2); qh[kt][3] = __float_as_uint(h3);
            ql[kt][0] = __float_as_uint(f2tf32(a0 - h0));
            ql[kt][1] = __float_as_uint(f2tf32(a1 - h1));
            ql[kt][2] = __float_as_uint(f2tf32(a2 - h2));
            ql[kt][3] = __float_as_uint(f2tf32(a3 - h3));
        }
    }
    __syncthreads();

    {
        float* Kd = KVbase;
        float* Vd = KVbase + KARR;
        #pragma unroll
        for (int i = 0; i < 8; i++) {
            int idx = tid + i * 256;
            int r = idx >> 5, c = (idx & 31) * 4;
            cp16(&Kd[r * LDK + c], Ksrc + (size_t)r * 128 + c);
            cp16(&Vd[r * LDK + c], Vsrc + (size_t)r * (NTOK * 2) + c);
        }
    }
    asm volatile("cp.async.commit_group;\n");

    float oacc[8][4];
    #pragma unroll
    for (int nt = 0; nt < 8; nt++)
        #pragma unroll
        for (int e = 0; e < 4; e++) oacc[nt][e] = 0.f;
    float m0 = -1e30f, m1 = -1e30f, l0 = 0.f, l1 = 0.f;

    int buf = 0;
    for (int j = 0; j < NKVT; j++) {
        if (j + 1 < NKVT) {
            float* Kd = KVbase + (buf ^ 1) * FLSTG;
            float* Vd = Kd + KARR;
            const float* kp = Ksrc + (size_t)(j + 1) * 64 * 128;
            const float* vp = Vsrc + (size_t)(j + 1) * 128;
            #pragma unroll
            for (int i = 0; i < 8; i++) {
                int idx = tid + i * 256;
                int r = idx >> 5, c = (idx & 31) * 4;
                cp16(&Kd[r * LDK + c], kp + (size_t)r * 128 + c);
                cp16(&Vd[r * LDK + c], vp + (size_t)r * (NTOK * 2) + c);
            }
            asm volatile("cp.async.commit_group;\n");
            asm volatile("cp.async.wait_group 1;\n");
        } else {
            asm volatile("cp.async.wait_group 0;\n");
        }
        __syncthreads();

        const float* Ks = KVbase + buf * FLSTG;
        const float* Vs = Ks + KARR;

        float sacc[8][4];
        #pragma unroll
        for (int nt = 0; nt < 8; nt++)
            #pragma unroll
            for (int e = 0; e < 4; e++) sacc[nt][e] = 0.f;
        #pragma unroll
        for (int kt = 0; kt < 8; kt++) {
            int kc2 = 2 * (kt * 8 + t);
            #pragma unroll
            for (int nt = 0; nt < 8; nt++) {
                const float* kr = Ks + (nt * 8 + g) * LDK + kc2;
                float2 b0 = *(const float2*)kr;
                float2 b1 = *(const float2*)(kr + 8);
                unsigned bh_[2] = {__float_as_uint(b0.x), __float_as_uint(b1.x)};
                unsigned bl_[2] = {__float_as_uint(b0.y), __float_as_uint(b1.y)};
                mma_tf32(sacc[nt], qh[kt], bh_);
                mma_tf32(sacc[nt], qh[kt], bl_);
                mma_tf32(sacc[nt], ql[kt], bh_);
            }
        }

        float mn0 = -1e30f, mn1 = -1e30f;
        #pragma unroll
        for (int nt = 0; nt < 8; nt++) {
            mn0 = fmaxf(mn0, fmaxf(sacc[nt][0], sacc[nt][1]));
            mn1 = fmaxf(mn1, fmaxf(sacc[nt][2], sacc[nt][3]));
        }
        mn0 = fmaxf(mn0, __shfl_xor_sync(0xffffffffu, mn0, 1));
        mn0 = fmaxf(mn0, __shfl_xor_sync(0xffffffffu, mn0, 2));
        mn1 = fmaxf(mn1, __shfl_xor_sync(0xffffffffu, mn1, 1));
        mn1 = fmaxf(mn1, __shfl_xor_sync(0xffffffffu, mn1, 2));
        float mN0 = fmaxf(m0, mn0), mN1 = fmaxf(m1, mn1);
        float f0 = __expf(m0 - mN0), f1 = __expf(m1 - mN1);
        float s0 = 0.f, s1 = 0.f;
        #pragma unroll
        for (int nt = 0; nt < 8; nt++) {
            sacc[nt][0] = __expf(sacc[nt][0] - mN0);
            sacc[nt][1] = __expf(sacc[nt][1] - mN0);
            sacc[nt][2] = __expf(sacc[nt][2] - mN1);
            sacc[nt][3] = __expf(sacc[nt][3] - mN1);
            s0 += sacc[nt][0] + sacc[nt][1];
            s1 += sacc[nt][2] + sacc[nt][3];
        }
        s0 += __shfl_xor_sync(0xffffffffu, s0, 1);
        s0 += __shfl_xor_sync(0xffffffffu, s0, 2);
        s1 += __shfl_xor_sync(0xffffffffu, s1, 1);
        s1 += __shfl_xor_sync(0xffffffffu, s1, 2);
        l0 = l0 * f0 + s0;
        l1 = l1 * f1 + s1;
        m0 = mN0; m1 = mN1;
        #pragma unroll
        for (int nt = 0; nt < 8; nt++) {
            oacc[nt][0] *= f0; oacc[nt][1] *= f0;
            oacc[nt][2] *= f1; oacc[nt][3] *= f1;
        }

        float* Pw = Ppad + warp * 16 * PW_LD;
        #pragma unroll
        for (int nt = 0; nt < 8; nt++) {
            *(float2*)&Pw[g * PW_LD + nt * 8 + 2 * t] = make_float2(sacc[nt][0], sacc[nt][1]);
            *(float2*)&Pw[(g + 8) * PW_LD + nt * 8 + 2 * t] = make_float2(sacc[nt][2], sacc[nt][3]);
        }
        __syncwarp();
        #pragma unroll
        for (int kt = 0; kt < 8; kt++) {
            int kc = kt * 8 + t;
            float a0 = Pw[g * PW_LD + kc];
            float a1 = Pw[(g + 8) * PW_LD + kc];
            float a2 = Pw[g * PW_LD + kc + 4];
            float a3 = Pw[(g + 8) * PW_LD + kc + 4];
            float h0 = f2tf32(a0), h1 = f2tf32(a1), h2 = f2tf32(a2), h3 = f2tf32(a3);
            unsigned ah_[4] = {__float_as_uint(h0), __float_as_uint(h1),
                               __float_as_uint(h2), __float_as_uint(h3)};
            unsigned al_[4] = {__float_as_uint(f2tf32(a0 - h0)), __float_as_uint(f2tf32(a1 - h1)),
                               __float_as_uint(f2tf32(a2 - h2)), __float_as_uint(f2tf32(a3 - h3))};
            int kc2 = 2 * kc;
            #pragma unroll
            for (int nt = 0; nt < 8; nt++) {
                const float* vr = Vs + (nt * 8 + g) * LDK + kc2;
                float2 b0 = *(const float2*)vr;
                float2 b1 = *(const float2*)(vr + 8);
                unsigned bh_[2] = {__float_as_uint(b0.x), __float_as_uint(b1.x)};
                unsigned bl_[2] = {__float_as_uint(b0.y), __float_as_uint(b1.y)};
                mma_tf32(oacc[nt], ah_, bh_);
                mma_tf32(oacc[nt], ah_, bl_);
                mma_tf32(oacc[nt], al_, bh_);
            }
        }
        __syncthreads();
        buf ^= 1;
    }

    // ---- fused epilogue: normalize, inverse transform (Mo=Pinv, sign=-1), store raw y ----
    float inv0 = 1.0f / l0, inv1 = 1.0f / l1;
    const int n0 = qb * 128 + warp * 16 + g;
    const int n1 = n0 + 8;
    const int cam = n0 >> 10;
    const float* Pi = g_Pinv + cam * 16;
    const int p0 = n0 & 1023, p1 = n1 & 1023;
    const float px0 = (float)(p0 & 31), py0 = (float)(p0 >> 5);
    const float px1 = (float)(p1 & 31), py1 = (float)(p1 >> 5);
    float* yrow0 = g_y + (size_t)n0 * CDIM + h * 64;
    float* yrow1 = g_y + (size_t)n1 * CDIM + h * 64;
    const int ib = (t & 1) * 2;
    #pragma unroll
    for (int nt = 0; nt < 8; nt++) {
        float a0 = oacc[nt][0] * inv0, b0 = oacc[nt][1] * inv0;
        float a1 = oacc[nt][2] * inv1, b1 = oacc[nt][3] * inv1;
        float o0e, o0o, o1e, o1o;
        if (nt < 4) {
            float q0 = __shfl_xor_sync(0xffffffffu, a0, 1);
            float q1 = __shfl_xor_sync(0xffffffffu, b0, 1);
            float r0 = __shfl_xor_sync(0xffffffffu, a1, 1);
            float r1 = __shfl_xor_sync(0xffffffffu, b1, 1);
            float v0[4], v1[4];
            if ((t & 1) == 0) {
                v0[0] = a0; v0[1] = b0; v0[2] = q0; v0[3] = q1;
                v1[0] = a1; v1[1] = b1; v1[2] = r0; v1[3] = r1;
            } else {
                v0[0] = q0; v0[1] = q1; v0[2] = a0; v0[3] = b0;
                v1[0] = r0; v1[1] = r1; v1[2] = a1; v1[3] = b1;
            }
            o0e = Pi[ib * 4 + 0] * v0[0] + Pi[ib * 4 + 1] * v0[1] + Pi[ib * 4 + 2] * v0[2] + Pi[ib * 4 + 3] * v0[3];
            o0o = Pi[(ib + 1) * 4 + 0] * v0[0] + Pi[(ib + 1) * 4 + 1] * v0[1] + Pi[(ib + 1) * 4 + 2] * v0[2] + Pi[(ib + 1) * 4 + 3] * v0[3];
            o1e = Pi[ib * 4 + 0] * v1[0] + Pi[ib * 4 + 1] * v1[1] + Pi[ib * 4 + 2] * v1[2] + Pi[ib * 4 + 3] * v1[3];
            o1o = Pi[(ib + 1) * 4 + 0] * v1[0] + Pi[(ib + 1) * 4 + 1] * v1[1] + Pi[(ib + 1) * 4 + 2] * v1[2] + Pi[(ib + 1) * 4 + 3] * v1[3];
        } else {
            int pair = 4 * nt + t - 16;
            float fr = g_freqs[pair & 7];
            float ang0 = ((pair < 8) ? px0 : py0) * fr;
            float c0 = cosf(ang0), s0 = sinf(ang0);
            o0e = a0 * c0 + b0 * s0;
            o0o = -a0 * s0 + b0 * c0;
            float ang1 = ((pair < 8) ? px1 : py1) * fr;
            float c1 = cosf(ang1), s1 = sinf(ang1);
            o1e = a1 * c1 + b1 * s1;
            o1o = -a1 * s1 + b1 * c1;
        }
        int off = 8 * nt + 2 * t;
        *(float2*)(yrow0 + off) = make_float2(o0e, o0o);
        *(float2*)(yrow1 + off) = make_float2(o1e, o1o);
    }
}

// ---------------- launch ----------------
extern "C" void kernel_launch(void* const* d_in, const int* in_sizes, int n_in,
                              void* d_out, int out_size) {
    const float* x      = (const float*)d_in[0];
    const float* ext    = (const float*)d_in[1];
    const float* Kmat   = (const float*)d_in[2];
    const float* qkv_w  = (const float*)d_in[3];
    const float* proj_w = (const float*)d_in[4];
    const float* proj_b = (const float*)d_in[5];
    float* out = (float*)d_out;

    static bool attr_done = false;
    if (!attr_done) {
        cudaFuncSetAttribute(gemm_nt_tf32, cudaFuncAttributeMaxDynamicSharedMemorySize, SM_NT);
        cudaFuncSetAttribute(flash_attn, cudaFuncAttributeMaxDynamicSharedMemorySize, FL_SMEM);
        attr_done = true;
    }

    void *p_qkv, *p_y;
    cudaGetSymbolAddress(&p_qkv, g_qkv);
    cudaGetSymbolAddress(&p_y, g_y);

    setup_mats<<<1, 32>>>(ext, Kmat);

    // QKV: [2048,3072] = x @ qkv_w^T
    gemm_nt_tf32<<<dim3(3072 / 128, 2048 / 128), 256, SM_NT>>>(
        x, qkv_w, (float*)p_qkv, NTOK, 3072, CDIM, nullptr);

    qkv_transform<<<NTOK * NHEADS / 4, 256>>>();

    // fused attention + output transform -> raw y
    flash_attn<<<dim3(NTOK / 128, NHEADS), 256, FL_SMEM>>>();

    // out = y @ proj_w^T + proj_b
    gemm_nt_tf32<<<dim3(1024 / 128, 2048 / 128), 256, SM_NT>>>(
        (const float*)p_y, proj_w, out, NTOK, CDIM, CDIM, proj_b);
}

// round 14
// speedup vs baseline: 1.0589x; 1.0589x over previous
#include <cuda_runtime.h>
#include <math.h>

#define NTOK 2048
#define CDIM 1024
#define NHEADS 16
#define HD 64
#define NCAM 2
#define NPER 1024
#define LDT 36

// ---------------- scratch ----------------
static __device__ float g_qkv[(size_t)NTOK * 3 * CDIM];
static __device__ float g_q[(size_t)NHEADS * NTOK * HD];
static __device__ float g_khl[(size_t)NHEADS * NTOK * HD * 2];   // [h][n][2d] hi/lo
static __device__ float g_vhl[(size_t)NHEADS * HD * NTOK * 2];   // [h][d][2n] hi/lo
static __device__ float g_y[(size_t)NTOK * CDIM];
static __device__ float g_P[NCAM * 16];
static __device__ float g_Pinv[NCAM * 16];
static __device__ float g_freqs[8];

// ---------------- helpers ----------------
__device__ __forceinline__ float f2tf32(float x) {
    unsigned u;
    asm("cvt.rna.tf32.f32 %0, %1;" : "=r"(u) : "f"(x));
    return __uint_as_float(u);
}
__device__ __forceinline__ void mma_tf32(float* d, const unsigned* a, const unsigned* b) {
    asm volatile(
        "mma.sync.aligned.m16n8k8.row.col.f32.tf32.tf32.f32 "
        "{%0,%1,%2,%3}, {%4,%5,%6,%7}, {%8,%9}, {%0,%1,%2,%3};\n"
        : "+f"(d[0]), "+f"(d[1]), "+f"(d[2]), "+f"(d[3])
        : "r"(a[0]), "r"(a[1]), "r"(a[2]), "r"(a[3]), "r"(b[0]), "r"(b[1]));
}
__device__ __forceinline__ void cp16(float* dst, const float* src) {
    unsigned d = (unsigned)__cvta_generic_to_shared(dst);
    asm volatile("cp.async.cg.shared.global [%0], [%1], 16;\n" :: "r"(d), "l"(src));
}

// ---------------- camera matrices + freq table ----------------
__global__ void setup_mats(const float* __restrict__ ext, const float* __restrict__ Ks) {
    int c = threadIdx.x;
    if (c < 8) g_freqs[c] = powf(100.f, -(float)c * 0.125f);
    if (c >= NCAM) return;
    const float sx = 2.0f / 448.0f, sy = 2.0f / 448.0f;
    float fx = Ks[c * 9 + 0], cx = Ks[c * 9 + 2];
    float fy = Ks[c * 9 + 4], cy = Ks[c * 9 + 5];
    float Kn[4][4] = {};
    Kn[0][0] = fx * sx; Kn[0][2] = cx * sx - 1.0f;
    Kn[1][1] = fy * sy; Kn[1][2] = cy * sy - 1.0f;
    Kn[2][2] = 1.0f;    Kn[3][3] = 1.0f;
    float P[4][4];
    for (int i = 0; i < 4; i++)
        for (int j = 0; j < 4; j++) {
            float s = 0.f;
            for (int k = 0; k < 4; k++) s += Kn[i][k] * ext[c * 16 + k * 4 + j];
            P[i][j] = s;
            g_P[c * 16 + i * 4 + j] = s;
        }
    float M[4][8];
    for (int i = 0; i < 4; i++)
        for (int j = 0; j < 4; j++) { M[i][j] = P[i][j]; M[i][4 + j] = (i == j) ? 1.f : 0.f; }
    for (int col = 0; col < 4; col++) {
        int piv = col;
        for (int r = col + 1; r < 4; r++)
            if (fabsf(M[r][col]) > fabsf(M[piv][col])) piv = r;
        if (piv != col)
            for (int j = 0; j < 8; j++) { float t = M[col][j]; M[col][j] = M[piv][j]; M[piv][j] = t; }
        float inv = 1.0f / M[col][col];
        for (int j = 0; j < 8; j++) M[col][j] *= inv;
        for (int r = 0; r < 4; r++) if (r != col) {
            float f = M[r][col];
            for (int j = 0; j < 8; j++) M[r][j] -= f * M[col][j];
        }
    }
    for (int i = 0; i < 4; i++)
        for (int j = 0; j < 4; j++) g_Pinv[c * 16 + i * 4 + j] = M[i][4 + j];
}

// ---------------- TF32x3 GEMM NT, BK=32, register double-buffered (R10 design) ----------------
#define GSTG (4 * 128 * LDT)
#define SM_NT (2 * GSTG * 4)
__global__ __launch_bounds__(256) void gemm_nt_tf32(
    const float* __restrict__ A, const float* __restrict__ B, float* __restrict__ C,
    int M, int N, int K, const float* __restrict__ bias)
{
    extern __shared__ float sm[];
    const int tid = threadIdx.x;
    const int lane = tid & 31, warp = tid >> 5;
    const int g = lane >> 2, t = lane & 3;
    const int wm = (warp >> 2) * 64, wn = (warp & 3) * 32;
    const int row0 = blockIdx.y * 128;
    const int col0 = blockIdx.x * 128;
    const int lr = tid >> 3;
    const int lc4 = (tid & 7) * 4;
    float acc[4][4][4];
    #pragma unroll
    for (int i = 0; i < 4; i++)
        #pragma unroll
        for (int j = 0; j < 4; j++)
            #pragma unroll
            for (int e = 0; e < 4; e++) acc[i][j][e] = 0.f;

    float4 avr[4], bvr[4];
    #pragma unroll
    for (int it = 0; it < 4; it++) {
        int r = lr + it * 32;
        avr[it] = *(const float4*)(A + (size_t)(row0 + r) * K + lc4);
        bvr[it] = *(const float4*)(B + (size_t)(col0 + r) * K + lc4);
    }
    {
        float* Ah = sm;
        float* Al = Ah + 128 * LDT;
        float* Bh = Al + 128 * LDT;
        float* Bl = Bh + 128 * LDT;
        #pragma unroll
        for (int it = 0; it < 4; it++) {
            int r = lr + it * 32;
            float4 av = avr[it], bv = bvr[it];
            float4 ah = {f2tf32(av.x), f2tf32(av.y), f2tf32(av.z), f2tf32(av.w)};
            float4 al = {f2tf32(av.x - ah.x), f2tf32(av.y - ah.y), f2tf32(av.z - ah.z), f2tf32(av.w - ah.w)};
            float4 bh = {f2tf32(bv.x), f2tf32(bv.y), f2tf32(bv.z), f2tf32(bv.w)};
            float4 bl = {f2tf32(bv.x - bh.x), f2tf32(bv.y - bh.y), f2tf32(bv.z - bh.z), f2tf32(bv.w - bh.w)};
            *(float4*)&Ah[r * LDT + lc4] = ah;
            *(float4*)&Al[r * LDT + lc4] = al;
            *(float4*)&Bh[r * LDT + lc4] = bh;
            *(float4*)&Bl[r * LDT + lc4] = bl;
        }
    }
    __syncthreads();

    int buf = 0;
    for (int kt = 0; kt < K; kt += 32) {
        bool more = (kt + 32 < K);
        if (more) {
            #pragma unroll
            for (int it = 0; it < 4; it++) {
                int r = lr + it * 32;
                avr[it] = *(const float4*)(A + (size_t)(row0 + r) * K + kt + 32 + lc4);
                bvr[it] = *(const float4*)(B + (size_t)(col0 + r) * K + kt + 32 + lc4);
            }
        }
        const float* Ah = sm + buf * GSTG;
        const float* Al = Ah + 128 * LDT;
        const float* Bh = Al + 128 * LDT;
        const float* Bl = Bh + 128 * LDT;
        #pragma unroll
        for (int kk = 0; kk < 4; kk++) {
            const int kc = kk * 8;
            unsigned bh_[4][2], bl_[4][2];
            #pragma unroll
            for (int nt = 0; nt < 4; nt++) {
                int nrow = (wn + nt * 8 + g) * LDT + kc + t;
                bh_[nt][0] = __float_as_uint(Bh[nrow]); bh_[nt][1] = __float_as_uint(Bh[nrow + 4]);
                bl_[nt][0] = __float_as_uint(Bl[nrow]); bl_[nt][1] = __float_as_uint(Bl[nrow + 4]);
            }
            #pragma unroll
            for (int mt = 0; mt < 4; mt++) {
                int r0 = (wm + mt * 16 + g) * LDT + kc + t;
                int r1 = (wm + mt * 16 + g + 8) * LDT + kc + t;
                unsigned ah_[4] = {__float_as_uint(Ah[r0]), __float_as_uint(Ah[r1]),
                                   __float_as_uint(Ah[r0 + 4]), __float_as_uint(Ah[r1 + 4])};
                unsigned al_[4] = {__float_as_uint(Al[r0]), __float_as_uint(Al[r1]),
                                   __float_as_uint(Al[r0 + 4]), __float_as_uint(Al[r1 + 4])};
                #pragma unroll
                for (int nt = 0; nt < 4; nt++) {
                    mma_tf32(acc[mt][nt], ah_, bh_[nt]);
                    mma_tf32(acc[mt][nt], ah_, bl_[nt]);
                    mma_tf32(acc[mt][nt], al_, bh_[nt]);
                }
            }
        }
        if (more) {
            float* Ah2 = sm + (buf ^ 1) * GSTG;
            float* Al2 = Ah2 + 128 * LDT;
            float* Bh2 = Al2 + 128 * LDT;
            float* Bl2 = Bh2 + 128 * LDT;
            #pragma unroll
            for (int it = 0; it < 4; it++) {
                int r = lr + it * 32;
                float4 av = avr[it], bv = bvr[it];
                float4 ah = {f2tf32(av.x), f2tf32(av.y), f2tf32(av.z), f2tf32(av.w)};
                float4 al = {f2tf32(av.x - ah.x), f2tf32(av.y - ah.y), f2tf32(av.z - ah.z), f2tf32(av.w - ah.w)};
                float4 bh = {f2tf32(bv.x), f2tf32(bv.y), f2tf32(bv.z), f2tf32(bv.w)};
                float4 bl = {f2tf32(bv.x - bh.x), f2tf32(bv.y - bh.y), f2tf32(bv.z - bh.z), f2tf32(bv.w - bh.w)};
                *(float4*)&Ah2[r * LDT + lc4] = ah;
                *(float4*)&Al2[r * LDT + lc4] = al;
                *(float4*)&Bh2[r * LDT + lc4] = bh;
                *(float4*)&Bl2[r * LDT + lc4] = bl;
            }
        }
        __syncthreads();
        buf ^= 1;
    }
    #pragma unroll
    for (int mt = 0; mt < 4; mt++) {
        int r = row0 + wm + mt * 16 + g;
        #pragma unroll
        for (int nt = 0; nt < 4; nt++) {
            int c = col0 + wn + nt * 8 + 2 * t;
            float b0 = 0.f, b1 = 0.f;
            if (bias) { b0 = bias[c]; b1 = bias[c + 1]; }
            float2 o0 = {acc[mt][nt][0] + b0, acc[mt][nt][1] + b1};
            float2 o1 = {acc[mt][nt][2] + b0, acc[mt][nt][3] + b1};
            *(float2*)(C + (size_t)r * N + c) = o0;
            *(float2*)(C + (size_t)(r + 8) * N + c) = o1;
        }
    }
}

// ---------------- q/k/v transform: Q pre-scaled, K/V pre-split hi/lo ----------------
__global__ __launch_bounds__(256) void qkv_transform() {
    int grp = threadIdx.x >> 6;
    int nh = blockIdx.x * 4 + grp;
    int n = nh >> 4;
    int h = nh & 15;
    int d = threadIdx.x & 63;
    __shared__ float sq[4][64], sk[4][64], sv[4][64];
    const float* base = g_qkv + (size_t)n * 3072 + h * 64;
    sq[grp][d] = base[d];
    sk[grp][d] = base[1024 + d];
    sv[grp][d] = base[2048 + d];
    __syncthreads();
    int cam = n / NPER;
    int p = n % NPER;
    float px = (float)(p & 31), py = (float)(p >> 5);
    float oq, ok, ov;
    if (d < 32) {
        int gg = d & ~3, i = d & 3;
        const float* P  = g_P + cam * 16;
        const float* Pi = g_Pinv + cam * 16;
        oq = ok = ov = 0.f;
        #pragma unroll
        for (int j = 0; j < 4; j++) {
            oq += Pi[j * 4 + i] * sq[grp][gg + j];
            float pij = P[i * 4 + j];
            ok += pij * sk[grp][gg + j];
            ov += pij * sv[grp][gg + j];
        }
    } else {
        int r = d - 32, pair = r >> 1, part = r & 1;
        float fr = g_freqs[pair & 7];
        float ang = ((pair < 8) ? px : py) * fr;
        float cc = cosf(ang), ss = sinf(ang);
        int ia = 32 + (pair << 1), ib = ia + 1;
        if (part == 0) { oq = sq[grp][ia] * cc - sq[grp][ib] * ss; ok = sk[grp][ia] * cc - sk[grp][ib] * ss; ov = sv[grp][ia] * cc - sv[grp][ib] * ss; }
        else           { oq = sq[grp][ia] * ss + sq[grp][ib] * cc; ok = sk[grp][ia] * ss + sk[grp][ib] * cc; ov = sv[grp][ia] * ss + sv[grp][ib] * cc; }
    }
    g_q[((size_t)h * NTOK + n) * HD + d] = oq * 0.125f;
    float kh = f2tf32(ok);
    float* kp = g_khl + ((size_t)h * NTOK + n) * 128 + 2 * d;
    kp[0] = kh; kp[1] = f2tf32(ok - kh);
    float vh = f2tf32(ov);
    float* vp = g_vhl + ((size_t)h * HD + d) * (NTOK * 2) + 2 * n;
    vp[0] = vh; vp[1] = f2tf32(ov - vh);
}

// ---------------- Flash attention with fused output transform (raw y) ----------------
#define LDK 136
#define KARR (64 * LDK)
#define FLSTG (2 * KARR)
#define PW_LD 68
#define PPAD (8 * 16 * PW_LD)
#define QLD 68
#define FL_SMEM ((PPAD + 2 * FLSTG) * 4)
#define NKVT (NTOK / 64)
__global__ __launch_bounds__(256, 1) void flash_attn() {
    extern __shared__ float sm[];
    float* Ppad = sm;
    float* KVbase = sm + PPAD;

    const int tid = threadIdx.x;
    const int lane = tid & 31, warp = tid >> 5;
    const int g = lane >> 2, t = lane & 3;
    const int h = blockIdx.y;
    const int qb = blockIdx.x;
    const float* Qg = g_q + ((size_t)h * NTOK + qb * 128) * HD;
    const float* Ksrc = g_khl + (size_t)h * NTOK * 128;
    const float* Vsrc = g_vhl + (size_t)h * HD * (NTOK * 2);

    {
        float* Qs = KVbase;
        int row = tid >> 1, halfq = tid & 1;
        #pragma unroll
        for (int i = 0; i < 4; i++) {
            float4 v = *(const float4*)(Qg + row * 64 + halfq * 32 + i * 8);
            float4 w = *(const float4*)(Qg + row * 64 + halfq * 32 + i * 8 + 4);
            *(float4*)&Qs[row * QLD + halfq * 32 + i * 8] = v;
            *(float4*)&Qs[row * QLD + halfq * 32 + i * 8 + 4] = w;
        }
    }
    __syncthreads();
    unsigned qh[8][4], ql[8][4];
    {
        const float* Qs = KVbase;
        int r0 = (warp * 16 + g) * QLD, r1 = (warp * 16 + g + 8) * QLD;
        #pragma unroll
        for (int kt = 0; kt < 8; kt++) {
            int c = kt * 8 + t;
            float a0 = Qs[r0 + c];
            float a1 = Qs[r1 + c];
            float a2 = Qs[r0 + c + 4];
            float a3 = Qs[r1 + c + 4];
            float h0 = f2tf32(a0), h1 = f2tf32(a1), h2 = f2tf32(a2), h3 = f2tf32(a3);
            qh[kt][0] = __float_as_uint(h0); qh[kt][1] = __float_as_uint(h1);
            qh[kt][2] = __float_as_uint(h2); qh[kt][3] = __float_as_uint(h3);
            ql[kt][0] = __float_as_uint(f2tf32(a0 - h0));
            ql[kt][1] = __float_as_uint(f2tf32(a1 - h1));
            ql[kt][2] = __float_as_uint(f2tf32(a2 - h2));
            ql[kt][3] = __float_as_uint(f2tf32(a3 - h3));
        }
    }
    __syncthreads();

    {
        float* Kd = KVbase;
        float* Vd = KVbase + KARR;
        #pragma unroll
        for (int i = 0; i < 8; i++) {
            int idx = tid + i * 256;
            int r = idx >> 5, c = (idx & 31) * 4;
            cp16(&Kd[r * LDK + c], Ksrc + (size_t)r * 128 + c);
            cp16(&Vd[r * LDK + c], Vsrc + (size_t)r * (NTOK * 2) + c);
        }
    }
    asm volatile("cp.async.commit_group;\n");

    float oacc[8][4];
    #pragma unroll
    for (int nt = 0; nt < 8; nt++)
        #pragma unroll
        for (int e = 0; e < 4; e++) oacc[nt][e] = 0.f;
    float m0 = -1e30f, m1 = -1e30f, l0 = 0.f, l1 = 0.f;

    int buf = 0;
    for (int j = 0; j < NKVT; j++) {
        if (j + 1 < NKVT) {
            float* Kd = KVbase + (buf ^ 1) * FLSTG;
            float* Vd = Kd + KARR;
            const float* kp = Ksrc + (size_t)(j + 1) * 64 * 128;
            const float* vp = Vsrc + (size_t)(j + 1) * 128;
            #pragma unroll
            for (int i = 0; i < 8; i++) {
                int idx = tid + i * 256;
                int r = idx >> 5, c = (idx & 31) * 4;
                cp16(&Kd[r * LDK + c], kp + (size_t)r * 128 + c);
                cp16(&Vd[r * LDK + c], vp + (size_t)r * (NTOK * 2) + c);
            }
            asm volatile("cp.async.commit_group;\n");
            asm volatile("cp.async.wait_group 1;\n");
        } else {
            asm volatile("cp.async.wait_group 0;\n");
        }
        __syncthreads();

        const float* Ks = KVbase + buf * FLSTG;
        const float* Vs = Ks + KARR;

        float sacc[8][4];
        #pragma unroll
        for (int nt = 0; nt < 8; nt++)
            #pragma unroll
            for (int e = 0; e < 4; e++) sacc[nt][e] = 0.f;
        #pragma unroll
        for (int kt = 0; kt < 8; kt++) {
            int kc2 = 2 * (kt * 8 + t);
            #pragma unroll
            for (int nt = 0; nt < 8; nt++) {
                const float* kr = Ks + (nt * 8 + g) * LDK + kc2;
                float2 b0 = *(const float2*)kr;
                float2 b1 = *(const float2*)(kr + 8);
                unsigned bh_[2] = {__float_as_uint(b0.x), __float_as_uint(b1.x)};
                unsigned bl_[2] = {__float_as_uint(b0.y), __float_as_uint(b1.y)};
                mma_tf32(sacc[nt], qh[kt], bh_);
                mma_tf32(sacc[nt], qh[kt], bl_);
                mma_tf32(sacc[nt], ql[kt], bh_);
            }
        }

        float mn0 = -1e30f, mn1 = -1e30f;
        #pragma unroll
        for (int nt = 0; nt < 8; nt++) {
            mn0 = fmaxf(mn0, fmaxf(sacc[nt][0], sacc[nt][1]));
            mn1 = fmaxf(mn1, fmaxf(sacc[nt][2], sacc[nt][3]));
        }
        mn0 = fmaxf(mn0, __shfl_xor_sync(0xffffffffu, mn0, 1));
        mn0 = fmaxf(mn0, __shfl_xor_sync(0xffffffffu, mn0, 2));
        mn1 = fmaxf(mn1, __shfl_xor_sync(0xffffffffu, mn1, 1));
        mn1 = fmaxf(mn1, __shfl_xor_sync(0xffffffffu, mn1, 2));
        float mN0 = fmaxf(m0, mn0), mN1 = fmaxf(m1, mn1);
        float f0 = __expf(m0 - mN0), f1 = __expf(m1 - mN1);
        float s0 = 0.f, s1 = 0.f;
        #pragma unroll
        for (int nt = 0; nt < 8; nt++) {
            sacc[nt][0] = __expf(sacc[nt][0] - mN0);
            sacc[nt][1] = __expf(sacc[nt][1] - mN0);
            sacc[nt][2] = __expf(sacc[nt][2] - mN1);
            sacc[nt][3] = __expf(sacc[nt][3] - mN1);
            s0 += sacc[nt][0] + sacc[nt][1];
            s1 += sacc[nt][2] + sacc[nt][3];
        }
        s0 += __shfl_xor_sync(0xffffffffu, s0, 1);
        s0 += __shfl_xor_sync(0xffffffffu, s0, 2);
        s1 += __shfl_xor_sync(0xffffffffu, s1, 1);
        s1 += __shfl_xor_sync(0xffffffffu, s1, 2);
        l0 = l0 * f0 + s0;
        l1 = l1 * f1 + s1;
        m0 = mN0; m1 = mN1;
        #pragma unroll
        for (int nt = 0; nt < 8; nt++) {
            oacc[nt][0] *= f0; oacc[nt][1] *= f0;
            oacc[nt][2] *= f1; oacc[nt][3] *= f1;
        }

        float* Pw = Ppad + warp * 16 * PW_LD;
        #pragma unroll
        for (int nt = 0; nt < 8; nt++) {
            *(float2*)&Pw[g * PW_LD + nt * 8 + 2 * t] = make_float2(sacc[nt][0], sacc[nt][1]);
            *(float2*)&Pw[(g + 8) * PW_LD + nt * 8 + 2 * t] = make_float2(sacc[nt][2], sacc[nt][3]);
        }
        __syncwarp();
        #pragma unroll
        for (int kt = 0; kt < 8; kt++) {
            int kc = kt * 8 + t;
            float a0 = Pw[g * PW_LD + kc];
            float a1 = Pw[(g + 8) * PW_LD + kc];
            float a2 = Pw[g * PW_LD + kc + 4];
            float a3 = Pw[(g + 8) * PW_LD + kc + 4];
            float h0 = f2tf32(a0), h1 = f2tf32(a1), h2 = f2tf32(a2), h3 = f2tf32(a3);
            unsigned ah_[4] = {__float_as_uint(h0), __float_as_uint(h1),
                               __float_as_uint(h2), __float_as_uint(h3)};
            unsigned al_[4] = {__float_as_uint(f2tf32(a0 - h0)), __float_as_uint(f2tf32(a1 - h1)),
                               __float_as_uint(f2tf32(a2 - h2)), __float_as_uint(f2tf32(a3 - h3))};
            int kc2 = 2 * kc;
            #pragma unroll
            for (int nt = 0; nt < 8; nt++) {
                const float* vr = Vs + (nt * 8 + g) * LDK + kc2;
                float2 b0 = *(const float2*)vr;
                float2 b1 = *(const float2*)(vr + 8);
                unsigned bh_[2] = {__float_as_uint(b0.x), __float_as_uint(b1.x)};
                unsigned bl_[2] = {__float_as_uint(b0.y), __float_as_uint(b1.y)};
                mma_tf32(oacc[nt], ah_, bh_);
                mma_tf32(oacc[nt], ah_, bl_);
                mma_tf32(oacc[nt], al_, bh_);
            }
        }
        __syncthreads();
        buf ^= 1;
    }

    // ---- fused epilogue: normalize, inverse transform (Mo=Pinv, sign=-1), store raw y ----
    float inv0 = 1.0f / l0, inv1 = 1.0f / l1;
    const int n0 = qb * 128 + warp * 16 + g;
    const int n1 = n0 + 8;
    const int cam = n0 >> 10;
    const float* Pi = g_Pinv + cam * 16;
    const int p0 = n0 & 1023, p1 = n1 & 1023;
    const float px0 = (float)(p0 & 31), py0 = (float)(p0 >> 5);
    const float px1 = (float)(p1 & 31), py1 = (float)(p1 >> 5);
    float* yrow0 = g_y + (size_t)n0 * CDIM + h * 64;
    float* yrow1 = g_y + (size_t)n1 * CDIM + h * 64;
    const int ib = (t & 1) * 2;
    #pragma unroll
    for (int nt = 0; nt < 8; nt++) {
        float a0 = oacc[nt][0] * inv0, b0 = oacc[nt][1] * inv0;
        float a1 = oacc[nt][2] * inv1, b1 = oacc[nt][3] * inv1;
        float o0e, o0o, o1e, o1o;
        if (nt < 4) {
            float q0 = __shfl_xor_sync(0xffffffffu, a0, 1);
            float q1 = __shfl_xor_sync(0xffffffffu, b0, 1);
            float r0 = __shfl_xor_sync(0xffffffffu, a1, 1);
            float r1 = __shfl_xor_sync(0xffffffffu, b1, 1);
            float v0[4], v1[4];
            if ((t & 1) == 0) {
                v0[0] = a0; v0[1] = b0; v0[2] = q0; v0[3] = q1;
                v1[0] = a1; v1[1] = b1; v1[2] = r0; v1[3] = r1;
            } else {
                v0[0] = q0; v0[1] = q1; v0[2] = a0; v0[3] = b0;
                v1[0] = r0; v1[1] = r1; v1[2] = a1; v1[3] = b1;
            }
            o0e = Pi[ib * 4 + 0] * v0[0] + Pi[ib * 4 + 1] * v0[1] + Pi[ib * 4 + 2] * v0[2] + Pi[ib * 4 + 3] * v0[3];
            o0o = Pi[(ib + 1) * 4 + 0] * v0[0] + Pi[(ib + 1) * 4 + 1] * v0[1] + Pi[(ib + 1) * 4 + 2] * v0[2] + Pi[(ib + 1) * 4 + 3] * v0[3];
            o1e = Pi[ib * 4 + 0] * v1[0] + Pi[ib * 4 + 1] * v1[1] + Pi[ib * 4 + 2] * v1[2] + Pi[ib * 4 + 3] * v1[3];
            o1o = Pi[(ib + 1) * 4 + 0] * v1[0] + Pi[(ib + 1) * 4 + 1] * v1[1] + Pi[(ib + 1) * 4 + 2] * v1[2] + Pi[(ib + 1) * 4 + 3] * v1[3];
        } else {
            int pair = 4 * nt + t - 16;
            float fr = g_freqs[pair & 7];
            float ang0 = ((pair < 8) ? px0 : py0) * fr;
            float c0 = cosf(ang0), s0 = sinf(ang0);
            o0e = a0 * c0 + b0 * s0;
            o0o = -a0 * s0 + b0 * c0;
            float ang1 = ((pair < 8) ? px1 : py1) * fr;
            float c1 = cosf(ang1), s1 = sinf(ang1);
            o1e = a1 * c1 + b1 * s1;
            o1o = -a1 * s1 + b1 * c1;
        }
        int off = 8 * nt + 2 * t;
        *(float2*)(yrow0 + off) = make_float2(o0e, o0o);
        *(float2*)(yrow1 + off) = make_float2(o1e, o1o);
    }
}

// ---------------- launch ----------------
extern "C" void kernel_launch(void* const* d_in, const int* in_sizes, int n_in,
                              void* d_out, int out_size) {
    const float* x      = (const float*)d_in[0];
    const float* ext    = (const float*)d_in[1];
    const float* Kmat   = (const float*)d_in[2];
    const float* qkv_w  = (const float*)d_in[3];
    const float* proj_w = (const float*)d_in[4];
    const float* proj_b = (const float*)d_in[5];
    float* out = (float*)d_out;

    static bool attr_done = false;
    if (!attr_done) {
        cudaFuncSetAttribute(gemm_nt_tf32, cudaFuncAttributeMaxDynamicSharedMemorySize, SM_NT);
        cudaFuncSetAttribute(flash_attn, cudaFuncAttributeMaxDynamicSharedMemorySize, FL_SMEM);
        attr_done = true;
    }

    void *p_qkv, *p_y;
    cudaGetSymbolAddress(&p_qkv, g_qkv);
    cudaGetSymbolAddress(&p_y, g_y);

    setup_mats<<<1, 32>>>(ext, Kmat);

    // QKV: [2048,3072] = x @ qkv_w^T
    gemm_nt_tf32<<<dim3(3072 / 128, 2048 / 128), 256, SM_NT>>>(
        x, qkv_w, (float*)p_qkv, NTOK, 3072, CDIM, nullptr);

    qkv_transform<<<NTOK * NHEADS / 4, 256>>>();

    // fused attention + output transform -> raw y
    flash_attn<<<dim3(NTOK / 128, NHEADS), 256, FL_SMEM>>>();

    // out = y @ proj_w^T + proj_b
    gemm_nt_tf32<<<dim3(1024 / 128, 2048 / 128), 256, SM_NT>>>(
        (const float*)p_y, proj_w, out, NTOK, CDIM, CDIM, proj_b);
}